// round 16
// baseline (speedup 1.0000x reference)
#include <cuda_runtime.h>

// PINN via register-resident jet table. 64 midpoint nodes (h=2^-6, centers
// (2j+1)/128), 12 floats/node = 3KB total -> lives in each warp's registers
// (lane L holds nodes L and L+32). Interp does NO table memory traffic:
// 24 SHFL.IDX + 12 SEL deliver the node jet to each lane; order-2 Taylor.
// Build kernel: order-6 jets, 8 threads/node, PDL into interp.
// Outputs: [u,u_x,u_xx,w,w_x,w_xx,w_xxx,w_xxxx].

#define KNODES 64
#define HINV   64.0f
#define XCSTEP 0.0078125f        // 1/128, exact
// node jet layout (12 floats): u0,u1,u2,u3,u4, w0,w1,w2,w3,w4,w5,w6
__device__ __align__(16) float4 g_tab[KNODES * 3];

__device__ __forceinline__ float tanh_fast(float z, float& s) {
    float e, r;
    asm("ex2.approx.f32 %0, %1;" : "=f"(e) : "f"(z * 2.8853900817779268f));
    asm("rcp.approx.f32 %0, %1;" : "=f"(r) : "f"(e + 1.0f));
    float t = fmaf(-2.0f, r, 1.0f);
    s = fmaf(-t, t, 1.0f);
    return t;
}

// ---------------- Kernel A: order-6 jets, 8 threads per node ----------------

__global__ __launch_bounds__(64)
void pinn_build_table(const float* __restrict__ gW0, const float* __restrict__ gb0,
                      const float* __restrict__ gW1, const float* __restrict__ gb1,
                      const float* __restrict__ gW2, const float* __restrict__ gb2)
{
    const unsigned FULL = 0xffffffffu;
    int gtid = blockIdx.x * blockDim.x + threadIdx.x;
    int node = gtid >> 3;
    int s    = gtid & 7;
    bool live = node < KNODES;
    int nodec = live ? node : KNODES - 1;

    const float x0 = (float)(2 * nodec + 1) * XCSTEP;   // midpoint, exact

    // Layer 0 jet for neuron s
    float h0, h1, h2, h3, h4, h5, h6;
    {
        float w = gW0[s];
        float z = fmaf(w, x0, gb0[s]);
        float sg;
        float t = tanh_fast(z, sg);
        float t2 = t * t;
        float d2 = -2.0f * t * sg;
        float d3 = sg * (6.0f * t2 - 2.0f);
        float d4 = t * sg * (16.0f - 24.0f * t2);
        float d5 = sg * (16.0f + t2 * (-120.0f + 120.0f * t2));
        float d6 = sg * t * (-272.0f + t2 * (960.0f - 720.0f * t2));
        float w2 = w * w, w3 = w2 * w;
        h0 = t;      h1 = sg * w;  h2 = d2 * w2; h3 = d3 * w3;
        h4 = d4 * w2 * w2; h5 = d5 * w2 * w3; h6 = d6 * w3 * w3;
    }

    // Layer 1 row s via width-8 shuffles
    float z0 = gb1[s], z1 = 0.f, z2 = 0.f, z3 = 0.f, z4 = 0.f, z5 = 0.f, z6 = 0.f;
#pragma unroll
    for (int k = 0; k < 8; ++k) {
        float wk = gW1[s * 8 + k];
        z0 = fmaf(wk, __shfl_sync(FULL, h0, k, 8), z0);
        z1 = fmaf(wk, __shfl_sync(FULL, h1, k, 8), z1);
        z2 = fmaf(wk, __shfl_sync(FULL, h2, k, 8), z2);
        z3 = fmaf(wk, __shfl_sync(FULL, h3, k, 8), z3);
        z4 = fmaf(wk, __shfl_sync(FULL, h4, k, 8), z4);
        z5 = fmaf(wk, __shfl_sync(FULL, h5, k, 8), z5);
        z6 = fmaf(wk, __shfl_sync(FULL, h6, k, 8), z6);
    }

    // tanh jet + Faa di Bruno to order 6
    float g0, g1, g2, g3, g4, g5, g6;
    {
        float sg;
        float t = tanh_fast(z0, sg);
        float t2 = t * t;
        float d1 = sg;
        float d2 = -2.0f * t * sg;
        float d3 = sg * (6.0f * t2 - 2.0f);
        float d4 = t * sg * (16.0f - 24.0f * t2);
        float d5 = sg * (16.0f + t2 * (-120.0f + 120.0f * t2));
        float d6 = sg * t * (-272.0f + t2 * (960.0f - 720.0f * t2));

        float z1_2 = z1 * z1, z1_3 = z1_2 * z1, z1_4 = z1_2 * z1_2;
        g0 = t;
        g1 = d1 * z1;
        g2 = d1 * z2 + d2 * z1_2;
        g3 = d1 * z3 + 3.0f * d2 * z1 * z2 + d3 * z1_3;
        g4 = d1 * z4 + d2 * (4.0f * z1 * z3 + 3.0f * z2 * z2)
           + 6.0f * d3 * z1_2 * z2 + d4 * z1_4;
        g5 = d1 * z5 + d2 * (5.0f * z1 * z4 + 10.0f * z2 * z3)
           + d3 * (10.0f * z1_2 * z3 + 15.0f * z1 * z2 * z2)
           + 10.0f * d4 * z1_3 * z2 + d5 * z1_4 * z1;
        g6 = d1 * z6 + d2 * (6.0f * z1 * z5 + 15.0f * z2 * z4 + 10.0f * z3 * z3)
           + d3 * (15.0f * z1_2 * z4 + 60.0f * z1 * z2 * z3 + 15.0f * z2 * z2 * z2)
           + d4 * (20.0f * z1_3 * z3 + 45.0f * z1_2 * z2 * z2)
           + 15.0f * d5 * z1_4 * z2 + d6 * z1_4 * z1_2;
    }

    // output taps + butterfly reduce over octet
    float wu = gW2[s], ww = gW2[8 + s];
    float U0 = wu * g0, U1 = wu * g1, U2 = wu * g2, U3 = wu * g3, U4 = wu * g4;
    float V0 = ww * g0, V1 = ww * g1, V2 = ww * g2, V3 = ww * g3,
          V4 = ww * g4, V5 = ww * g5, V6 = ww * g6;
#pragma unroll
    for (int off = 4; off >= 1; off >>= 1) {
        U0 += __shfl_xor_sync(FULL, U0, off, 8);
        U1 += __shfl_xor_sync(FULL, U1, off, 8);
        U2 += __shfl_xor_sync(FULL, U2, off, 8);
        U3 += __shfl_xor_sync(FULL, U3, off, 8);
        U4 += __shfl_xor_sync(FULL, U4, off, 8);
        V0 += __shfl_xor_sync(FULL, V0, off, 8);
        V1 += __shfl_xor_sync(FULL, V1, off, 8);
        V2 += __shfl_xor_sync(FULL, V2, off, 8);
        V3 += __shfl_xor_sync(FULL, V3, off, 8);
        V4 += __shfl_xor_sync(FULL, V4, off, 8);
        V5 += __shfl_xor_sync(FULL, V5, off, 8);
        V6 += __shfl_xor_sync(FULL, V6, off, 8);
    }
    U0 += gb2[0];
    V0 += gb2[1];

    if (live && s < 3) {
        float4 v;
        switch (s) {
            case 0:  v = make_float4(U0, U1, U2, U3); break;
            case 1:  v = make_float4(U4, V0, V1, V2); break;
            default: v = make_float4(V3, V4, V5, V6); break;
        }
        g_tab[node * 3 + s] = v;
    }

    asm volatile("griddepcontrol.launch_dependents;");
}

// ---------------- Kernel B: register-table shuffle interp ------------------

#define IB    256
#define ITER  16          // passes per warp; warp covers 512 points

__global__ __launch_bounds__(IB)
void pinn_interp(const float* __restrict__ x, float* __restrict__ out, int n)
{
    const unsigned FULL = 0xffffffffu;
    const int lane = threadIdx.x & 31;
    const int wid  = (blockIdx.x * IB + threadIdx.x) >> 5;
    const int wbase = wid * (32 * ITER);

    // Wait for the build kernel's table (PDL).
    asm volatile("griddepcontrol.wait;");

    // Load the whole table into warp registers: lane L holds nodes L, L+32.
    float a[12], b[12];
    {
        float4 A0 = g_tab[lane * 3 + 0];
        float4 A1 = g_tab[lane * 3 + 1];
        float4 A2 = g_tab[lane * 3 + 2];
        float4 B0 = g_tab[(lane + 32) * 3 + 0];
        float4 B1 = g_tab[(lane + 32) * 3 + 1];
        float4 B2 = g_tab[(lane + 32) * 3 + 2];
        a[0]=A0.x; a[1]=A0.y; a[2]=A0.z; a[3]=A0.w;
        a[4]=A1.x; a[5]=A1.y; a[6]=A1.z; a[7]=A1.w;
        a[8]=A2.x; a[9]=A2.y; a[10]=A2.z; a[11]=A2.w;
        b[0]=B0.x; b[1]=B0.y; b[2]=B0.z; b[3]=B0.w;
        b[4]=B1.x; b[5]=B1.y; b[6]=B1.z; b[7]=B1.w;
        b[8]=B2.x; b[9]=B2.y; b[10]=B2.z; b[11]=B2.w;
    }

    const bool full = (wbase + 32 * ITER) <= n;
    if (wbase >= n) return;

    // software-pipelined x load (1 pass ahead)
    int p0 = wbase + lane;
    float xv = __ldg(x + (full ? p0 : min(p0, n - 1)));

#pragma unroll
    for (int i = 0; i < ITER; ++i) {
        int p = wbase + i * 32 + lane;
        float xcur = xv;
        if (i + 1 < ITER) {
            int pn = wbase + (i + 1) * 32 + lane;
            xv = __ldg(x + (full ? pn : min(pn, n - 1)));
        }

        // node index + local offset (dx exact via fma)
        int j = (int)(xcur * HINV);                  // 0..63
        float dx = fmaf((float)(2 * j + 1), -XCSTEP, xcur);
        float dx2 = 0.5f * dx * dx;
        int src = j & 31;
        bool hi = j >= 32;

        // fetch node jet via shuffles (no memory)
        float c[12];
#pragma unroll
        for (int k = 0; k < 12; ++k) {
            float va = __shfl_sync(FULL, a[k], src);
            float vb = __shfl_sync(FULL, b[k], src);
            c[k] = hi ? vb : va;
        }

        // order-2 Taylor, 8 outputs
        float o0 = fmaf(dx2, c[2],  fmaf(dx, c[1],  c[0]));   // u
        float o1 = fmaf(dx2, c[3],  fmaf(dx, c[2],  c[1]));   // u_x
        float o2 = fmaf(dx2, c[4],  fmaf(dx, c[3],  c[2]));   // u_xx
        float o3 = fmaf(dx2, c[7],  fmaf(dx, c[6],  c[5]));   // w
        float o4 = fmaf(dx2, c[8],  fmaf(dx, c[7],  c[6]));   // w_x
        float o5 = fmaf(dx2, c[9],  fmaf(dx, c[8],  c[7]));   // w_xx
        float o6 = fmaf(dx2, c[10], fmaf(dx, c[9],  c[8]));   // w_xxx
        float o7 = fmaf(dx2, c[11], fmaf(dx, c[10], c[9]));   // w_xxxx

        if (full || p < n) {
            float4* op = reinterpret_cast<float4*>(out + (size_t)p * 8);
            op[0] = make_float4(o0, o1, o2, o3);
            op[1] = make_float4(o4, o5, o6, o7);
        }
    }
}

extern "C" void kernel_launch(void* const* d_in, const int* in_sizes, int n_in,
                              void* d_out, int out_size)
{
    const float* x  = (const float*)d_in[0];
    const float* W0 = (const float*)d_in[1];
    const float* b0 = (const float*)d_in[2];
    const float* W1 = (const float*)d_in[3];
    const float* b1 = (const float*)d_in[4];
    const float* W2 = (const float*)d_in[5];
    const float* b2 = (const float*)d_in[6];
    float* out = (float*)d_out;

    int n = in_sizes[0];

    // Build: 64 nodes x 8 lanes = 512 threads over 8 small blocks.
    pinn_build_table<<<8, 64>>>(W0, b0, W1, b1, W2, b2);

    // Interp with PDL.
    int pts_per_block = (IB / 32) * 32 * ITER;   // 4096
    int blocks = (n + pts_per_block - 1) / pts_per_block;

    cudaLaunchConfig_t cfg = {};
    cfg.gridDim  = dim3((unsigned)blocks, 1, 1);
    cfg.blockDim = dim3(IB, 1, 1);
    cfg.dynamicSmemBytes = 0;
    cfg.stream = 0;
    cudaLaunchAttribute attrs[1];
    attrs[0].id = cudaLaunchAttributeProgrammaticStreamSerialization;
    attrs[0].val.programmaticStreamSerializationAllowed = 1;
    cfg.attrs = attrs;
    cfg.numAttrs = 1;

    cudaLaunchKernelEx(&cfg, pinn_interp, x, out, n);
}

// round 17
// speedup vs baseline: 1.3057x; 1.3057x over previous
#include <cuda_runtime.h>

// PINN via register-resident jet table. 64 midpoint nodes (h=2^-6, centers
// (2j+1)/128), 12 floats/node = 3KB -> in each warp's registers (lane L
// holds nodes L and L+32). Interp: NO table memory traffic; 24 SHFL.IDX +
// 12 SEL per 32 points deliver node jets; order-2 Taylor. This round: high
// block count + 2 points/lane for ILP (R16 was grid/latency-starved).
// Build kernel: order-6 jets, 8 threads/node, PDL into interp.
// Outputs: [u,u_x,u_xx,w,w_x,w_xx,w_xxx,w_xxxx].

#define KNODES 64
#define HINV   64.0f
#define XCSTEP 0.0078125f        // 1/128, exact
__device__ __align__(16) float4 g_tab[KNODES * 3];

__device__ __forceinline__ float tanh_fast(float z, float& s) {
    float e, r;
    asm("ex2.approx.f32 %0, %1;" : "=f"(e) : "f"(z * 2.8853900817779268f));
    asm("rcp.approx.f32 %0, %1;" : "=f"(r) : "f"(e + 1.0f));
    float t = fmaf(-2.0f, r, 1.0f);
    s = fmaf(-t, t, 1.0f);
    return t;
}

// ---------------- Kernel A: order-6 jets, 8 threads per node ----------------

__global__ __launch_bounds__(64)
void pinn_build_table(const float* __restrict__ gW0, const float* __restrict__ gb0,
                      const float* __restrict__ gW1, const float* __restrict__ gb1,
                      const float* __restrict__ gW2, const float* __restrict__ gb2)
{
    const unsigned FULL = 0xffffffffu;
    int gtid = blockIdx.x * blockDim.x + threadIdx.x;
    int node = gtid >> 3;
    int s    = gtid & 7;
    bool live = node < KNODES;
    int nodec = live ? node : KNODES - 1;

    const float x0 = (float)(2 * nodec + 1) * XCSTEP;   // midpoint, exact

    float h0, h1, h2, h3, h4, h5, h6;
    {
        float w = gW0[s];
        float z = fmaf(w, x0, gb0[s]);
        float sg;
        float t = tanh_fast(z, sg);
        float t2 = t * t;
        float d2 = -2.0f * t * sg;
        float d3 = sg * (6.0f * t2 - 2.0f);
        float d4 = t * sg * (16.0f - 24.0f * t2);
        float d5 = sg * (16.0f + t2 * (-120.0f + 120.0f * t2));
        float d6 = sg * t * (-272.0f + t2 * (960.0f - 720.0f * t2));
        float w2 = w * w, w3 = w2 * w;
        h0 = t;      h1 = sg * w;  h2 = d2 * w2; h3 = d3 * w3;
        h4 = d4 * w2 * w2; h5 = d5 * w2 * w3; h6 = d6 * w3 * w3;
    }

    float z0 = gb1[s], z1 = 0.f, z2 = 0.f, z3 = 0.f, z4 = 0.f, z5 = 0.f, z6 = 0.f;
#pragma unroll
    for (int k = 0; k < 8; ++k) {
        float wk = gW1[s * 8 + k];
        z0 = fmaf(wk, __shfl_sync(FULL, h0, k, 8), z0);
        z1 = fmaf(wk, __shfl_sync(FULL, h1, k, 8), z1);
        z2 = fmaf(wk, __shfl_sync(FULL, h2, k, 8), z2);
        z3 = fmaf(wk, __shfl_sync(FULL, h3, k, 8), z3);
        z4 = fmaf(wk, __shfl_sync(FULL, h4, k, 8), z4);
        z5 = fmaf(wk, __shfl_sync(FULL, h5, k, 8), z5);
        z6 = fmaf(wk, __shfl_sync(FULL, h6, k, 8), z6);
    }

    float g0, g1, g2, g3, g4, g5, g6;
    {
        float sg;
        float t = tanh_fast(z0, sg);
        float t2 = t * t;
        float d1 = sg;
        float d2 = -2.0f * t * sg;
        float d3 = sg * (6.0f * t2 - 2.0f);
        float d4 = t * sg * (16.0f - 24.0f * t2);
        float d5 = sg * (16.0f + t2 * (-120.0f + 120.0f * t2));
        float d6 = sg * t * (-272.0f + t2 * (960.0f - 720.0f * t2));

        float z1_2 = z1 * z1, z1_3 = z1_2 * z1, z1_4 = z1_2 * z1_2;
        g0 = t;
        g1 = d1 * z1;
        g2 = d1 * z2 + d2 * z1_2;
        g3 = d1 * z3 + 3.0f * d2 * z1 * z2 + d3 * z1_3;
        g4 = d1 * z4 + d2 * (4.0f * z1 * z3 + 3.0f * z2 * z2)
           + 6.0f * d3 * z1_2 * z2 + d4 * z1_4;
        g5 = d1 * z5 + d2 * (5.0f * z1 * z4 + 10.0f * z2 * z3)
           + d3 * (10.0f * z1_2 * z3 + 15.0f * z1 * z2 * z2)
           + 10.0f * d4 * z1_3 * z2 + d5 * z1_4 * z1;
        g6 = d1 * z6 + d2 * (6.0f * z1 * z5 + 15.0f * z2 * z4 + 10.0f * z3 * z3)
           + d3 * (15.0f * z1_2 * z4 + 60.0f * z1 * z2 * z3 + 15.0f * z2 * z2 * z2)
           + d4 * (20.0f * z1_3 * z3 + 45.0f * z1_2 * z2 * z2)
           + 15.0f * d5 * z1_4 * z2 + d6 * z1_4 * z1_2;
    }

    float wu = gW2[s], ww = gW2[8 + s];
    float U0 = wu * g0, U1 = wu * g1, U2 = wu * g2, U3 = wu * g3, U4 = wu * g4;
    float V0 = ww * g0, V1 = ww * g1, V2 = ww * g2, V3 = ww * g3,
          V4 = ww * g4, V5 = ww * g5, V6 = ww * g6;
#pragma unroll
    for (int off = 4; off >= 1; off >>= 1) {
        U0 += __shfl_xor_sync(FULL, U0, off, 8);
        U1 += __shfl_xor_sync(FULL, U1, off, 8);
        U2 += __shfl_xor_sync(FULL, U2, off, 8);
        U3 += __shfl_xor_sync(FULL, U3, off, 8);
        U4 += __shfl_xor_sync(FULL, U4, off, 8);
        V0 += __shfl_xor_sync(FULL, V0, off, 8);
        V1 += __shfl_xor_sync(FULL, V1, off, 8);
        V2 += __shfl_xor_sync(FULL, V2, off, 8);
        V3 += __shfl_xor_sync(FULL, V3, off, 8);
        V4 += __shfl_xor_sync(FULL, V4, off, 8);
        V5 += __shfl_xor_sync(FULL, V5, off, 8);
        V6 += __shfl_xor_sync(FULL, V6, off, 8);
    }
    U0 += gb2[0];
    V0 += gb2[1];

    if (live && s < 3) {
        float4 v;
        switch (s) {
            case 0:  v = make_float4(U0, U1, U2, U3); break;
            case 1:  v = make_float4(U4, V0, V1, V2); break;
            default: v = make_float4(V3, V4, V5, V6); break;
        }
        g_tab[node * 3 + s] = v;
    }

    asm volatile("griddepcontrol.launch_dependents;");
}

// ---------------- Kernel B: register-table shuffle interp, 2pt/lane --------

#define IB    256
#define ITER  2           // iters per warp; each iter covers 64 points
// points per block = (IB/32) * 64 * ITER = 1024

__device__ __forceinline__ void jet_fetch(const unsigned FULL,
                                          const float* a, const float* b,
                                          int src, bool hi, float* c)
{
#pragma unroll
    for (int k = 0; k < 12; ++k) {
        float va = __shfl_sync(FULL, a[k], src);
        float vb = __shfl_sync(FULL, b[k], src);
        c[k] = hi ? vb : va;
    }
}

__device__ __forceinline__ void taylor_store(float dx, const float* c,
                                             float* __restrict__ out, int p)
{
    float dx2 = 0.5f * dx * dx;
    float o0 = fmaf(dx2, c[2],  fmaf(dx, c[1],  c[0]));
    float o1 = fmaf(dx2, c[3],  fmaf(dx, c[2],  c[1]));
    float o2 = fmaf(dx2, c[4],  fmaf(dx, c[3],  c[2]));
    float o3 = fmaf(dx2, c[7],  fmaf(dx, c[6],  c[5]));
    float o4 = fmaf(dx2, c[8],  fmaf(dx, c[7],  c[6]));
    float o5 = fmaf(dx2, c[9],  fmaf(dx, c[8],  c[7]));
    float o6 = fmaf(dx2, c[10], fmaf(dx, c[9],  c[8]));
    float o7 = fmaf(dx2, c[11], fmaf(dx, c[10], c[9]));
    float4* op = reinterpret_cast<float4*>(out + (size_t)p * 8);
    op[0] = make_float4(o0, o1, o2, o3);
    op[1] = make_float4(o4, o5, o6, o7);
}

__global__ __launch_bounds__(IB)
void pinn_interp(const float* __restrict__ x, float* __restrict__ out, int n)
{
    const unsigned FULL = 0xffffffffu;
    const int lane = threadIdx.x & 31;
    const int wid  = (blockIdx.x * IB + threadIdx.x) >> 5;
    const int wbase = wid * (64 * ITER);

    asm volatile("griddepcontrol.wait;");

    // table: lane L holds nodes L (a) and L+32 (b)
    float a[12], b[12];
    {
        float4 A0 = g_tab[lane * 3 + 0];
        float4 A1 = g_tab[lane * 3 + 1];
        float4 A2 = g_tab[lane * 3 + 2];
        float4 B0 = g_tab[(lane + 32) * 3 + 0];
        float4 B1 = g_tab[(lane + 32) * 3 + 1];
        float4 B2 = g_tab[(lane + 32) * 3 + 2];
        a[0]=A0.x; a[1]=A0.y; a[2]=A0.z; a[3]=A0.w;
        a[4]=A1.x; a[5]=A1.y; a[6]=A1.z; a[7]=A1.w;
        a[8]=A2.x; a[9]=A2.y; a[10]=A2.z; a[11]=A2.w;
        b[0]=B0.x; b[1]=B0.y; b[2]=B0.z; b[3]=B0.w;
        b[4]=B1.x; b[5]=B1.y; b[6]=B1.z; b[7]=B1.w;
        b[8]=B2.x; b[9]=B2.y; b[10]=B2.z; b[11]=B2.w;
    }

    if (wbase >= n) return;
    const bool full = (wbase + 64 * ITER) <= n;

    // prefetch iter 0 (two points per lane: +lane, +32+lane)
    float xa, xb;
    {
        int p0 = wbase + lane, p1 = wbase + 32 + lane;
        xa = __ldg(x + (full ? p0 : min(p0, n - 1)));
        xb = __ldg(x + (full ? p1 : min(p1, n - 1)));
    }

#pragma unroll
    for (int i = 0; i < ITER; ++i) {
        float x0 = xa, x1 = xb;
        if (i + 1 < ITER) {
            int p0 = wbase + (i + 1) * 64 + lane;
            int p1 = p0 + 32;
            xa = __ldg(x + (full ? p0 : min(p0, n - 1)));
            xb = __ldg(x + (full ? p1 : min(p1, n - 1)));
        }

        // index math for both points
        int j0 = (int)(x0 * HINV);
        int j1 = (int)(x1 * HINV);
        float dx0 = fmaf((float)(2 * j0 + 1), -XCSTEP, x0);
        float dx1 = fmaf((float)(2 * j1 + 1), -XCSTEP, x1);
        int src0 = j0 & 31, src1 = j1 & 31;
        bool hi0 = j0 >= 32, hi1 = j1 >= 32;

        // two independent shuffle chains (ILP)
        float c0[12], c1[12];
        jet_fetch(FULL, a, b, src0, hi0, c0);
        jet_fetch(FULL, a, b, src1, hi1, c1);

        int p0 = wbase + i * 64 + lane;
        int p1 = p0 + 32;
        if (full) {
            taylor_store(dx0, c0, out, p0);
            taylor_store(dx1, c1, out, p1);
        } else {
            if (p0 < n) taylor_store(dx0, c0, out, p0);
            if (p1 < n) taylor_store(dx1, c1, out, p1);
        }
    }
}

extern "C" void kernel_launch(void* const* d_in, const int* in_sizes, int n_in,
                              void* d_out, int out_size)
{
    const float* x  = (const float*)d_in[0];
    const float* W0 = (const float*)d_in[1];
    const float* b0 = (const float*)d_in[2];
    const float* W1 = (const float*)d_in[3];
    const float* b1 = (const float*)d_in[4];
    const float* W2 = (const float*)d_in[5];
    const float* b2 = (const float*)d_in[6];
    float* out = (float*)d_out;

    int n = in_sizes[0];

    pinn_build_table<<<8, 64>>>(W0, b0, W1, b1, W2, b2);

    int pts_per_block = (IB / 32) * 64 * ITER;   // 1024
    int blocks = (n + pts_per_block - 1) / pts_per_block;

    cudaLaunchConfig_t cfg = {};
    cfg.gridDim  = dim3((unsigned)blocks, 1, 1);
    cfg.blockDim = dim3(IB, 1, 1);
    cfg.dynamicSmemBytes = 0;
    cfg.stream = 0;
    cudaLaunchAttribute attrs[1];
    attrs[0].id = cudaLaunchAttributeProgrammaticStreamSerialization;
    attrs[0].val.programmaticStreamSerializationAllowed = 1;
    cfg.attrs = attrs;
    cfg.numAttrs = 1;

    cudaLaunchKernelEx(&cfg, pinn_interp, x, out, n);
}